// round 11
// baseline (speedup 1.0000x reference)
#include <cuda_runtime.h>
#include <math.h>

#define BATCH 8
#define REG   400
#define TLEN  1200
#define NB    5
#define NPSI  1024
#define LMAX  544

#define NOUT  TLEN
#define XOFF  288                  // left zero pad in shared X (even)
#define SHX   1920
#define DMAX  576                  // padded taps per (b,k)
#define DH    288                  // tap pairs (quads)

static __device__ float4 d_D4[BATCH * NB][DH];  // (De,De,Do,Do) per tap pair
static __device__ int    d_LD[BATCH * NB];      // kept tap count
static __device__ int    d_OFF[BATCH * NB];     // adjusted (off - 1), EVEN
static __device__ float  d_SQS[BATCH * NB];     // sqrt(scale)

// ---------------------------------------------------------------------------
// packed fp32x2 helpers
// ---------------------------------------------------------------------------
__device__ __forceinline__ void fma2(unsigned long long &a,
                                     unsigned long long x,
                                     unsigned long long d) {
    asm("fma.rn.f32x2 %0, %1, %2, %0;" : "+l"(a) : "l"(x), "l"(d));
}
__device__ __forceinline__ unsigned long long lds64(unsigned sa) {
    unsigned long long v;
    asm("ld.shared.b64 %0, [%1];" : "=l"(v) : "r"(sa));
    return v;
}
__device__ __forceinline__ void lds128(unsigned sa, unsigned long long &a,
                                       unsigned long long &b) {
    asm("ld.shared.v2.u64 {%0,%1}, [%2];" : "=l"(a), "=l"(b) : "r"(sa));
}

// ---------------------------------------------------------------------------
// Kernel 1: INT_PSI (fp32 scan) + per-(b,k) taps + Gaussian-tail truncation
//           + parity-aligned lo + duplicated-quad packing + freq bands.
// ---------------------------------------------------------------------------
__global__ void k_prep(const float* __restrict__ tr,
                       const float* __restrict__ lsp,
                       const float* __restrict__ bwp,
                       float* __restrict__ out_bands) {
    __shared__ float sp[NPSI];
    __shared__ float shK[LMAX + 1];
    __shared__ float shDt[DMAX];
    __shared__ int   s_lo, s_hi;

    const int bk = blockIdx.x;
    const int b  = bk / NB;
    const int k  = bk % NB;
    const int i  = threadIdx.x;

    const float STEP_F = (float)(16.0 / 1023.0);

    for (int idx = i; idx < NPSI; idx += DMAX) {
        float x = -8.0f + STEP_F * (float)idx;
        sp[idx] = expf(-0.5f * x * x) * cosf(5.0f * x);
    }
    __syncthreads();
    for (int o = 1; o < NPSI; o <<= 1) {
        float a0 = 0.0f, a1 = 0.0f;
        int i1 = i + DMAX;
        if (i >= o) a0 = sp[i - o];
        if (i1 < NPSI && i1 >= o) a1 = sp[i1 - o];
        __syncthreads();
        sp[i] += a0;
        if (i1 < NPSI) sp[i1] += a1;
        __syncthreads();
    }

    const float trf   = tr[b] / 2.0f;
    const float scale = expf(lsp[k]) / trf;
    const float sstep = scale * STEP_F;
    const int   L0    = (int)floorf(scale * 16.0f) + 2;

    bool m = false;
    if (i < LMAX) {
        int j = (int)floorf((float)i / sstep);
        m = (i < L0) && (j < NPSI);
        int jc = min(max(j, 0), NPSI - 1);
        shK[i] = m ? sp[jc] * STEP_F : 0.0f;
    } else if (i == LMAX) {
        shK[LMAX] = 0.0f;
    }
    if (i == 0) { s_lo = DMAX; s_hi = -1; }
    const int L = __syncthreads_count(m);   // mask is a prefix

    float dv = 0.0f;
    if (i <= L) {
        float prev = (i == 0) ? 0.0f : shK[i - 1];
        dv = prev - shK[i];
    }
    shDt[i] = dv;
    __syncthreads();

    // significant range (exclude the boundary tap i == L; |D[L]| ~ 9.3e-6)
    const float thr = 1e-4f / scale;
    if (i < L && fabsf(shDt[i]) > thr) {
        atomicMin(&s_lo, i);
        atomicMax(&s_hi, i);
    }
    __syncthreads();

    const int base = (L - 2) / 2 + 1 - L;              // (off - 1) before lo
    int lo, hi;
    if (s_hi >= s_lo) { lo = s_lo; hi = s_hi; }
    else              { lo = 0;    hi = L;    }        // degenerate fallback
    // force OFF = base + lo EVEN (parity fold: X windows always even-aligned)
    if (((base + lo) & 1) != 0) lo = (lo > 0) ? lo - 1 : lo + 1;
    const int newLD = hi - lo + 1;

    // pack duplicated quads: quad q = (D[2q],D[2q],D[2q+1],D[2q+1]), zero-pad
    if (i < DH) {
        int e_i = 2 * i, o_i = 2 * i + 1;
        float e = (e_i < newLD) ? shDt[lo + e_i] : 0.0f;
        float o = (o_i < newLD) ? shDt[lo + o_i] : 0.0f;
        d_D4[bk][i] = make_float4(e, e, o, o);
    }

    if (i == 0) {
        d_LD[bk]  = newLD;
        d_OFF[bk] = base + lo;                          // even
        d_SQS[bk] = sqrtf(scale);
        float center = 1.0f / (scale * tr[b]);
        float bw = bwp[k];
        out_bands[bk * 2 + 0] = fmaxf(0.008f, center * (1.0f - bw * 0.5f));
        out_bands[bk * 2 + 1] = fminf(0.12f,  center * (1.0f + bw * 0.5f));
    }
}

// ---------------------------------------------------------------------------
// Kernel 2: FIR, packed f32x2, polyphase-fused, software-pipelined D loads.
// TWO rows per block (256 threads): both halves share one tap staging and
// the per-band barriers; identical tap lengths -> perfectly balanced halves.
// Static 288-quad staging (compile-time trip count, the proven-fast form).
// ---------------------------------------------------------------------------
__global__ void __launch_bounds__(256, 3)
k_cwt(const float* __restrict__ ts, float* __restrict__ out) {
    const int bp   = blockIdx.x;           // row-pair id
    const int b    = bp / (REG / 2);
    const int tid  = threadIdx.x;
    const int half = tid >> 7;              // 0 or 1
    const int wg   = tid & 127;             // lane within half
    const int row  = bp * 2 + half;         // global (b,r) row

    __shared__ __align__(16) float  shXA[2][SHX];
    __shared__ __align__(16) float4 shD4[DH];
    __shared__ float shV[2][132];

    // zero + load both rows: each half owns its own X buffer
    for (int idx = wg; idx < SHX; idx += 128) shXA[half][idx] = 0.0f;
    __syncthreads();
    {
        const float* __restrict__ xrow = ts + (size_t)row * TLEN;
        for (int idx = wg; idx < TLEN; idx += 128)
            shXA[half][XOFF + idx] = xrow[idx];
    }
    // stage band 0's quads (static trip count; all 256 threads)
    {
        const float4* __restrict__ dsrc = d_D4[b * NB];
        for (int idx = tid; idx < DH; idx += 256) shD4[idx] = dsrc[idx];
    }
    __syncthreads();

    float* __restrict__ outbase = out + (size_t)row * NB * NOUT;

    const unsigned aXA = (unsigned)__cvta_generic_to_shared(&shXA[half][0]);
    const unsigned aD4 = (unsigned)__cvta_generic_to_shared(shD4);

    for (int k = 0; k < NB; k++) {
        const int   bk  = b * NB + k;
        const int   LD  = d_LD[bk];
        const int   off = d_OFF[bk];
        const float sq  = d_SQS[bk];

        const int m0 = XOFF + off + 10 * wg;       // even by construction
        unsigned pX = aXA + 4u * (unsigned)m0;
        unsigned pD = aD4;

        const int S  = (LD + 1) >> 1;              // tap pairs
        const int S6 = ((S + 5) / 6) * 6;          // zero-tap padded

        unsigned long long E0 = 0, E1 = 0, E2 = 0, E3 = 0, E4 = 0;
        unsigned long long V0 = 0, V1 = 0, V2 = 0, V3 = 0, V4 = 0;

        unsigned long long W0 = lds64(pX + 0);
        unsigned long long W1 = lds64(pX + 8);
        unsigned long long W2 = lds64(pX + 16);
        unsigned long long W3 = lds64(pX + 24);
        unsigned long long W4 = lds64(pX + 32);
        unsigned long long W5 = lds64(pX + 40);

        unsigned long long dEa, dOa, dEb, dOb;
        lds128(pD, dEa, dOa);                      // step-0 quad preload

#define FMAS(Q0, Q1, Q2, Q3, Q4, DE, DO)                                 \
        fma2(E0, Q0, DE); fma2(V0, Q0, DO);                              \
        fma2(E1, Q1, DE); fma2(V1, Q1, DO);                              \
        fma2(E2, Q2, DE); fma2(V2, Q2, DO);                              \
        fma2(E3, Q3, DE); fma2(V3, Q3, DO);                              \
        fma2(E4, Q4, DE); fma2(V4, Q4, DO);

        for (int it = 0; it < S6; it += 6) {
            lds128(pD + 16, dEb, dOb);             // prefetch step 1
            FMAS(W0, W1, W2, W3, W4, dEa, dOa)     // step 0
            W0 = lds64(pX + 48);
            lds128(pD + 32, dEa, dOa);             // prefetch step 2
            FMAS(W1, W2, W3, W4, W5, dEb, dOb)     // step 1
            W1 = lds64(pX + 56);
            lds128(pD + 48, dEb, dOb);             // prefetch step 3
            FMAS(W2, W3, W4, W5, W0, dEa, dOa)     // step 2
            W2 = lds64(pX + 64);
            lds128(pD + 64, dEa, dOa);             // prefetch step 4
            FMAS(W3, W4, W5, W0, W1, dEb, dOb)     // step 3
            W3 = lds64(pX + 72);
            lds128(pD + 80, dEb, dOb);             // prefetch step 5
            FMAS(W4, W5, W0, W1, W2, dEa, dOa)     // step 4
            W4 = lds64(pX + 80);
            lds128(pD + 96, dEa, dOa);             // prefetch next group step 0
            FMAS(W5, W0, W1, W2, W3, dEb, dOb)     // step 5
            W5 = lds64(pX + 88);

            pX += 48;
            pD += 96;
        }
#undef FMAS

        // exchange V0.lo with neighbor thread (within the same half)
        shV[half][wg] = ((float2*)&V0)->x;
        __syncthreads();

        if (wg < 120) {
            const float vlast = shV[half][wg + 1];   // V[10*wg+10]
            float2* __restrict__ o2 =
                (float2*)(outbase + (size_t)k * NOUT + 10 * wg);
            float2 e, va, vb, r;
            e = *(float2*)&E0; va = *(float2*)&V0; vb = *(float2*)&V1;
            r.x = sq * fabsf(e.x + va.y); r.y = sq * fabsf(e.y + vb.x); o2[0] = r;
            e = *(float2*)&E1; va = vb; vb = *(float2*)&V2;
            r.x = sq * fabsf(e.x + va.y); r.y = sq * fabsf(e.y + vb.x); o2[1] = r;
            e = *(float2*)&E2; va = vb; vb = *(float2*)&V3;
            r.x = sq * fabsf(e.x + va.y); r.y = sq * fabsf(e.y + vb.x); o2[2] = r;
            e = *(float2*)&E3; va = vb; vb = *(float2*)&V4;
            r.x = sq * fabsf(e.x + va.y); r.y = sq * fabsf(e.y + vb.x); o2[3] = r;
            e = *(float2*)&E4; va = *(float2*)&V4;
            r.x = sq * fabsf(e.x + va.y); r.y = sq * fabsf(e.y + vlast); o2[4] = r;
        }

        // stage next band's quads (static trip count; epilogue never reads shD4)
        if (k + 1 < NB) {
            const float4* __restrict__ dsrc = d_D4[bk + 1];
            for (int idx = tid; idx < DH; idx += 256) shD4[idx] = dsrc[idx];
        }
        __syncthreads();
    }
}

// ---------------------------------------------------------------------------
extern "C" void kernel_launch(void* const* d_in, const int* in_sizes, int n_in,
                              void* d_out, int out_size) {
    (void)in_sizes; (void)n_in; (void)out_size;
    const float* ts  = (const float*)d_in[0];
    const float* tr  = (const float*)d_in[1];
    const float* lsp = (const float*)d_in[2];
    const float* bwp = (const float*)d_in[3];
    float* out = (float*)d_out;

    float* bands = out + (size_t)BATCH * REG * NB * NOUT;

    k_prep<<<BATCH * NB, DMAX>>>(tr, lsp, bwp, bands);
    k_cwt<<<BATCH * REG / 2, 256>>>(ts, out);
}

// round 12
// speedup vs baseline: 1.1867x; 1.1867x over previous
#include <cuda_runtime.h>
#include <math.h>

#define BATCH 8
#define REG   400
#define TLEN  1200
#define NB    5
#define NPSI  1024
#define LMAX  544

#define NOUT  TLEN
#define XOFF  288                  // left zero pad in shared X (even)
#define SHX   1920
#define DMAX  576                  // padded taps per (b,k)
#define DH    288                  // tap pairs

static __device__ float d_D[BATCH * NB][DMAX];
static __device__ int   d_LD[BATCH * NB];   // kept tap count
static __device__ int   d_OFF[BATCH * NB];  // adjusted (off - 1), EVEN
static __device__ float d_SQS[BATCH * NB];  // sqrt(scale)

// ---------------------------------------------------------------------------
// packed fp32x2 helpers
// ---------------------------------------------------------------------------
__device__ __forceinline__ void fma2(unsigned long long &a,
                                     unsigned long long x,
                                     unsigned long long d) {
    asm("fma.rn.f32x2 %0, %1, %2, %0;" : "+l"(a) : "l"(x), "l"(d));
}
__device__ __forceinline__ unsigned long long lds64(unsigned sa) {
    unsigned long long v;
    asm("ld.shared.b64 %0, [%1];" : "=l"(v) : "r"(sa));
    return v;
}
__device__ __forceinline__ void lds128(unsigned sa, unsigned long long &a,
                                       unsigned long long &b) {
    asm("ld.shared.v2.u64 {%0,%1}, [%2];" : "=l"(a), "=l"(b) : "r"(sa));
}

// ---------------------------------------------------------------------------
// Kernel 1: INT_PSI (fp32 scan) + per-(b,k) taps + Gaussian-tail truncation
//           + parity-aligned lo + freq bands.  (R7's k_prep + even-OFF fold)
// ---------------------------------------------------------------------------
__global__ void k_prep(const float* __restrict__ tr,
                       const float* __restrict__ lsp,
                       const float* __restrict__ bwp,
                       float* __restrict__ out_bands) {
    __shared__ float sp[NPSI];
    __shared__ float shK[LMAX + 1];
    __shared__ float shDt[DMAX];
    __shared__ int   s_lo, s_hi;

    const int bk = blockIdx.x;
    const int b  = bk / NB;
    const int k  = bk % NB;
    const int i  = threadIdx.x;

    const float STEP_F = (float)(16.0 / 1023.0);

    for (int idx = i; idx < NPSI; idx += DMAX) {
        float x = -8.0f + STEP_F * (float)idx;
        sp[idx] = expf(-0.5f * x * x) * cosf(5.0f * x);
    }
    __syncthreads();
    for (int o = 1; o < NPSI; o <<= 1) {
        float a0 = 0.0f, a1 = 0.0f;
        int i1 = i + DMAX;
        if (i >= o) a0 = sp[i - o];
        if (i1 < NPSI && i1 >= o) a1 = sp[i1 - o];
        __syncthreads();
        sp[i] += a0;
        if (i1 < NPSI) sp[i1] += a1;
        __syncthreads();
    }

    const float trf   = tr[b] / 2.0f;
    const float scale = expf(lsp[k]) / trf;
    const float sstep = scale * STEP_F;
    const int   L0    = (int)floorf(scale * 16.0f) + 2;

    bool m = false;
    if (i < LMAX) {
        int j = (int)floorf((float)i / sstep);
        m = (i < L0) && (j < NPSI);
        int jc = min(max(j, 0), NPSI - 1);
        shK[i] = m ? sp[jc] * STEP_F : 0.0f;
    } else if (i == LMAX) {
        shK[LMAX] = 0.0f;
    }
    if (i == 0) { s_lo = DMAX; s_hi = -1; }
    const int L = __syncthreads_count(m);   // mask is a prefix

    float dv = 0.0f;
    if (i <= L) {
        float prev = (i == 0) ? 0.0f : shK[i - 1];
        dv = prev - shK[i];
    }
    shDt[i] = dv;
    __syncthreads();

    // significant range (exclude the boundary tap i == L; |D[L]| ~ 9.3e-6)
    const float thr = 1e-4f / scale;
    if (i < L && fabsf(shDt[i]) > thr) {
        atomicMin(&s_lo, i);
        atomicMax(&s_hi, i);
    }
    __syncthreads();

    const int base = (L - 2) / 2 + 1 - L;              // (off - 1) before lo
    int lo, hi;
    if (s_hi >= s_lo) { lo = s_lo; hi = s_hi; }
    else              { lo = 0;    hi = L;    }        // degenerate fallback
    // force OFF = base + lo EVEN (parity fold: X windows always even-aligned)
    if (((base + lo) & 1) != 0) lo = (lo > 0) ? lo - 1 : lo + 1;
    const int newLD = hi - lo + 1;

    d_D[bk][i] = (i < newLD) ? shDt[i + lo] : 0.0f;    // zero-padded tail

    if (i == 0) {
        d_LD[bk]  = newLD;
        d_OFF[bk] = base + lo;                          // even
        d_SQS[bk] = sqrtf(scale);
        float center = 1.0f / (scale * tr[b]);
        float bw = bwp[k];
        out_bands[bk * 2 + 0] = fmaxf(0.008f, center * (1.0f - bw * 0.5f));
        out_bands[bk * 2 + 1] = fminf(0.12f,  center * (1.0f + bw * 0.5f));
    }
}

// ---------------------------------------------------------------------------
// Kernel 2: FIR, packed f32x2, polyphase-fused, software-pipelined D loads.
// R7 verbatim except: (a) single X buffer (OFF always even), (b) exact-S
// predicated tail instead of rounding the step count up to a multiple of 6.
// ---------------------------------------------------------------------------
__global__ void __launch_bounds__(128, 7)
k_cwt(const float* __restrict__ ts, float* __restrict__ out) {
    const int br  = blockIdx.x;
    const int b   = br / REG;
    const int tid = threadIdx.x;

    __shared__ __align__(16) float  shXA[SHX];
    __shared__ __align__(16) float4 shD4[DH];
    __shared__ float shV[129];

    for (int idx = tid; idx < SHX; idx += 128) shXA[idx] = 0.0f;
    __syncthreads();
    const float* __restrict__ xrow = ts + (size_t)br * TLEN;
    for (int idx = tid; idx < TLEN; idx += 128) shXA[XOFF + idx] = xrow[idx];

    // stage band 0's taps (static trip count, R7 form)
    {
        const float2* __restrict__ dsrc = (const float2*)d_D[b * NB];
        for (int idx = tid; idx < DH; idx += 128) {
            float2 p = dsrc[idx];
            shD4[idx] = make_float4(p.x, p.x, p.y, p.y);
        }
    }
    __syncthreads();

    float* __restrict__ outbase = out + (size_t)br * NB * NOUT;

    const unsigned aXA = (unsigned)__cvta_generic_to_shared(shXA);
    const unsigned aD4 = (unsigned)__cvta_generic_to_shared(shD4);

    for (int k = 0; k < NB; k++) {
        const int   bk  = b * NB + k;
        const int   LD  = d_LD[bk];
        const int   off = d_OFF[bk];
        const float sq  = d_SQS[bk];

        const int m0 = XOFF + off + 10 * tid;      // even by construction
        unsigned pX = aXA + 4u * (unsigned)m0;
        unsigned pD = aD4;

        const int S      = (LD + 1) >> 1;          // tap pairs (exact)
        const int S_full = (S / 6) * 6;            // full 6-step groups
        const int r      = S - S_full;             // tail steps, 0..5

        unsigned long long E0 = 0, E1 = 0, E2 = 0, E3 = 0, E4 = 0;
        unsigned long long V0 = 0, V1 = 0, V2 = 0, V3 = 0, V4 = 0;

        unsigned long long W0 = lds64(pX + 0);
        unsigned long long W1 = lds64(pX + 8);
        unsigned long long W2 = lds64(pX + 16);
        unsigned long long W3 = lds64(pX + 24);
        unsigned long long W4 = lds64(pX + 32);
        unsigned long long W5 = lds64(pX + 40);

        unsigned long long dEa, dOa, dEb, dOb;
        lds128(pD, dEa, dOa);                      // step-0 quad preload

#define FMAS(Q0, Q1, Q2, Q3, Q4, DE, DO)                                 \
        fma2(E0, Q0, DE); fma2(V0, Q0, DO);                              \
        fma2(E1, Q1, DE); fma2(V1, Q1, DO);                              \
        fma2(E2, Q2, DE); fma2(V2, Q2, DO);                              \
        fma2(E3, Q3, DE); fma2(V3, Q3, DO);                              \
        fma2(E4, Q4, DE); fma2(V4, Q4, DO);

        for (int it = 0; it < S_full; it += 6) {
            lds128(pD + 16, dEb, dOb);             // prefetch step 1
            FMAS(W0, W1, W2, W3, W4, dEa, dOa)     // step 0
            W0 = lds64(pX + 48);
            lds128(pD + 32, dEa, dOa);             // prefetch step 2
            FMAS(W1, W2, W3, W4, W5, dEb, dOb)     // step 1
            W1 = lds64(pX + 56);
            lds128(pD + 48, dEb, dOb);             // prefetch step 3
            FMAS(W2, W3, W4, W5, W0, dEa, dOa)     // step 2
            W2 = lds64(pX + 64);
            lds128(pD + 64, dEa, dOa);             // prefetch step 4
            FMAS(W3, W4, W5, W0, W1, dEb, dOb)     // step 3
            W3 = lds64(pX + 72);
            lds128(pD + 80, dEb, dOb);             // prefetch step 5
            FMAS(W4, W5, W0, W1, W2, dEa, dOa)     // step 4
            W4 = lds64(pX + 80);
            lds128(pD + 96, dEa, dOa);             // prefetch next group step 0
            FMAS(W5, W0, W1, W2, W3, dEb, dOb)     // step 5
            W5 = lds64(pX + 88);

            pX += 48;
            pD += 96;
        }

        // exact tail: first r steps of a group (rotation is 0 at entry;
        // uniform branches, taps beyond S are zero-padded so prefetch reads
        // past the end are harmless)
        if (r > 0) {
            lds128(pD + 16, dEb, dOb);
            FMAS(W0, W1, W2, W3, W4, dEa, dOa)
            if (r > 1) {
                W0 = lds64(pX + 48);
                lds128(pD + 32, dEa, dOa);
                FMAS(W1, W2, W3, W4, W5, dEb, dOb)
                if (r > 2) {
                    W1 = lds64(pX + 56);
                    lds128(pD + 48, dEb, dOb);
                    FMAS(W2, W3, W4, W5, W0, dEa, dOa)
                    if (r > 3) {
                        W2 = lds64(pX + 64);
                        lds128(pD + 64, dEa, dOa);
                        FMAS(W3, W4, W5, W0, W1, dEb, dOb)
                        if (r > 4) {
                            W3 = lds64(pX + 72);
                            FMAS(W4, W5, W0, W1, W2, dEa, dOa)
                        }
                    }
                }
            }
        }
#undef FMAS

        // exchange V0.lo with neighbor thread
        shV[tid] = ((float2*)&V0)->x;
        __syncthreads();

        if (tid < 120) {
            const float vlast = shV[tid + 1];   // V[10t+10]
            float2* __restrict__ o2 =
                (float2*)(outbase + (size_t)k * NOUT + 10 * tid);
            float2 e, va, vb, rr;
            e = *(float2*)&E0; va = *(float2*)&V0; vb = *(float2*)&V1;
            rr.x = sq * fabsf(e.x + va.y); rr.y = sq * fabsf(e.y + vb.x); o2[0] = rr;
            e = *(float2*)&E1; va = vb; vb = *(float2*)&V2;
            rr.x = sq * fabsf(e.x + va.y); rr.y = sq * fabsf(e.y + vb.x); o2[1] = rr;
            e = *(float2*)&E2; va = vb; vb = *(float2*)&V3;
            rr.x = sq * fabsf(e.x + va.y); rr.y = sq * fabsf(e.y + vb.x); o2[2] = rr;
            e = *(float2*)&E3; va = vb; vb = *(float2*)&V4;
            rr.x = sq * fabsf(e.x + va.y); rr.y = sq * fabsf(e.y + vb.x); o2[3] = rr;
            e = *(float2*)&E4; va = *(float2*)&V4;
            rr.x = sq * fabsf(e.x + va.y); rr.y = sq * fabsf(e.y + vlast); o2[4] = rr;
        }

        // stage next band's taps (static trip count; epilogue never reads shD4)
        if (k + 1 < NB) {
            const float2* __restrict__ dsrc = (const float2*)d_D[bk + 1];
            for (int idx = tid; idx < DH; idx += 128) {
                float2 p = dsrc[idx];
                shD4[idx] = make_float4(p.x, p.x, p.y, p.y);
            }
        }
        __syncthreads();
    }
}

// ---------------------------------------------------------------------------
extern "C" void kernel_launch(void* const* d_in, const int* in_sizes, int n_in,
                              void* d_out, int out_size) {
    (void)in_sizes; (void)n_in; (void)out_size;
    const float* ts  = (const float*)d_in[0];
    const float* tr  = (const float*)d_in[1];
    const float* lsp = (const float*)d_in[2];
    const float* bwp = (const float*)d_in[3];
    float* out = (float*)d_out;

    float* bands = out + (size_t)BATCH * REG * NB * NOUT;

    k_prep<<<BATCH * NB, DMAX>>>(tr, lsp, bwp, bands);
    k_cwt<<<BATCH * REG, 128>>>(ts, out);
}

// round 13
// speedup vs baseline: 1.2006x; 1.0117x over previous
#include <cuda_runtime.h>
#include <math.h>

#define BATCH 8
#define REG   400
#define TLEN  1200
#define NB    5
#define NPSI  1024
#define LMAX  544

#define NOUT  TLEN
#define XOFF  288                  // left zero pad in shared X (even)
#define SHX   1920
#define DMAX  576                  // padded taps per (b,k)
#define DH    288                  // tap pairs

static __device__ float d_D[BATCH * NB][DMAX];
static __device__ int   d_LD[BATCH * NB];   // kept tap count
static __device__ int   d_OFF[BATCH * NB];  // adjusted (off - 1), EVEN
static __device__ float d_SQS[BATCH * NB];  // sqrt(scale)

// ---------------------------------------------------------------------------
// packed fp32x2 helpers
// ---------------------------------------------------------------------------
__device__ __forceinline__ void fma2(unsigned long long &a,
                                     unsigned long long x,
                                     unsigned long long d) {
    asm("fma.rn.f32x2 %0, %1, %2, %0;" : "+l"(a) : "l"(x), "l"(d));
}
__device__ __forceinline__ unsigned long long lds64(unsigned sa) {
    unsigned long long v;
    asm("ld.shared.b64 %0, [%1];" : "=l"(v) : "r"(sa));
    return v;
}
__device__ __forceinline__ void lds128(unsigned sa, unsigned long long &a,
                                       unsigned long long &b) {
    asm("ld.shared.v2.u64 {%0,%1}, [%2];" : "=l"(a), "=l"(b) : "r"(sa));
}

// ---------------------------------------------------------------------------
// Kernel 1: INT_PSI (fp32 scan) + per-(b,k) taps + Gaussian-tail truncation
//           + parity-aligned lo + freq bands.  (R7's k_prep + even-OFF fold)
// ---------------------------------------------------------------------------
__global__ void k_prep(const float* __restrict__ tr,
                       const float* __restrict__ lsp,
                       const float* __restrict__ bwp,
                       float* __restrict__ out_bands) {
    __shared__ float sp[NPSI];
    __shared__ float shK[LMAX + 1];
    __shared__ float shDt[DMAX];
    __shared__ int   s_lo, s_hi;

    const int bk = blockIdx.x;
    const int b  = bk / NB;
    const int k  = bk % NB;
    const int i  = threadIdx.x;

    const float STEP_F = (float)(16.0 / 1023.0);

    for (int idx = i; idx < NPSI; idx += DMAX) {
        float x = -8.0f + STEP_F * (float)idx;
        sp[idx] = expf(-0.5f * x * x) * cosf(5.0f * x);
    }
    __syncthreads();
    for (int o = 1; o < NPSI; o <<= 1) {
        float a0 = 0.0f, a1 = 0.0f;
        int i1 = i + DMAX;
        if (i >= o) a0 = sp[i - o];
        if (i1 < NPSI && i1 >= o) a1 = sp[i1 - o];
        __syncthreads();
        sp[i] += a0;
        if (i1 < NPSI) sp[i1] += a1;
        __syncthreads();
    }

    const float trf   = tr[b] / 2.0f;
    const float scale = expf(lsp[k]) / trf;
    const float sstep = scale * STEP_F;
    const int   L0    = (int)floorf(scale * 16.0f) + 2;

    bool m = false;
    if (i < LMAX) {
        int j = (int)floorf((float)i / sstep);
        m = (i < L0) && (j < NPSI);
        int jc = min(max(j, 0), NPSI - 1);
        shK[i] = m ? sp[jc] * STEP_F : 0.0f;
    } else if (i == LMAX) {
        shK[LMAX] = 0.0f;
    }
    if (i == 0) { s_lo = DMAX; s_hi = -1; }
    const int L = __syncthreads_count(m);   // mask is a prefix

    float dv = 0.0f;
    if (i <= L) {
        float prev = (i == 0) ? 0.0f : shK[i - 1];
        dv = prev - shK[i];
    }
    shDt[i] = dv;
    __syncthreads();

    // significant range (exclude the boundary tap i == L; |D[L]| ~ 9.3e-6)
    const float thr = 1e-4f / scale;
    if (i < L && fabsf(shDt[i]) > thr) {
        atomicMin(&s_lo, i);
        atomicMax(&s_hi, i);
    }
    __syncthreads();

    const int base = (L - 2) / 2 + 1 - L;              // (off - 1) before lo
    int lo, hi;
    if (s_hi >= s_lo) { lo = s_lo; hi = s_hi; }
    else              { lo = 0;    hi = L;    }        // degenerate fallback
    // force OFF = base + lo EVEN (parity fold: X windows always even-aligned)
    if (((base + lo) & 1) != 0) lo = (lo > 0) ? lo - 1 : lo + 1;
    const int newLD = hi - lo + 1;

    d_D[bk][i] = (i < newLD) ? shDt[i + lo] : 0.0f;    // zero-padded tail

    if (i == 0) {
        d_LD[bk]  = newLD;
        d_OFF[bk] = base + lo;                          // even
        d_SQS[bk] = sqrtf(scale);
        float center = 1.0f / (scale * tr[b]);
        float bw = bwp[k];
        out_bands[bk * 2 + 0] = fmaxf(0.008f, center * (1.0f - bw * 0.5f));
        out_bands[bk * 2 + 1] = fminf(0.12f,  center * (1.0f + bw * 0.5f));
    }
}

// ---------------------------------------------------------------------------
// Kernel 2: FIR, packed f32x2, polyphase-fused, software-pipelined D loads.
// R7 verbatim except: (a) single X buffer (OFF always even), (b) exact-S
// predicated tail instead of rounding the step count up to a multiple of 6.
// ---------------------------------------------------------------------------
__global__ void __launch_bounds__(128, 7)
k_cwt(const float* __restrict__ ts, float* __restrict__ out) {
    const int br  = blockIdx.x;
    const int b   = br / REG;
    const int tid = threadIdx.x;

    __shared__ __align__(16) float  shXA[SHX];
    __shared__ __align__(16) float4 shD4[DH];
    __shared__ float shV[129];

    for (int idx = tid; idx < SHX; idx += 128) shXA[idx] = 0.0f;
    __syncthreads();
    const float* __restrict__ xrow = ts + (size_t)br * TLEN;
    for (int idx = tid; idx < TLEN; idx += 128) shXA[XOFF + idx] = xrow[idx];

    // stage band 0's taps (static trip count, R7 form)
    {
        const float2* __restrict__ dsrc = (const float2*)d_D[b * NB];
        for (int idx = tid; idx < DH; idx += 128) {
            float2 p = dsrc[idx];
            shD4[idx] = make_float4(p.x, p.x, p.y, p.y);
        }
    }
    __syncthreads();

    float* __restrict__ outbase = out + (size_t)br * NB * NOUT;

    const unsigned aXA = (unsigned)__cvta_generic_to_shared(shXA);
    const unsigned aD4 = (unsigned)__cvta_generic_to_shared(shD4);

    for (int k = 0; k < NB; k++) {
        const int   bk  = b * NB + k;
        const int   LD  = d_LD[bk];
        const int   off = d_OFF[bk];
        const float sq  = d_SQS[bk];

        const int m0 = XOFF + off + 10 * tid;      // even by construction
        unsigned pX = aXA + 4u * (unsigned)m0;
        unsigned pD = aD4;

        const int S      = (LD + 1) >> 1;          // tap pairs (exact)
        const int S_full = (S / 6) * 6;            // full 6-step groups
        const int r      = S - S_full;             // tail steps, 0..5

        unsigned long long E0 = 0, E1 = 0, E2 = 0, E3 = 0, E4 = 0;
        unsigned long long V0 = 0, V1 = 0, V2 = 0, V3 = 0, V4 = 0;

        unsigned long long W0 = lds64(pX + 0);
        unsigned long long W1 = lds64(pX + 8);
        unsigned long long W2 = lds64(pX + 16);
        unsigned long long W3 = lds64(pX + 24);
        unsigned long long W4 = lds64(pX + 32);
        unsigned long long W5 = lds64(pX + 40);

        unsigned long long dEa, dOa, dEb, dOb;
        lds128(pD, dEa, dOa);                      // step-0 quad preload

#define FMAS(Q0, Q1, Q2, Q3, Q4, DE, DO)                                 \
        fma2(E0, Q0, DE); fma2(V0, Q0, DO);                              \
        fma2(E1, Q1, DE); fma2(V1, Q1, DO);                              \
        fma2(E2, Q2, DE); fma2(V2, Q2, DO);                              \
        fma2(E3, Q3, DE); fma2(V3, Q3, DO);                              \
        fma2(E4, Q4, DE); fma2(V4, Q4, DO);

        for (int it = 0; it < S_full; it += 6) {
            lds128(pD + 16, dEb, dOb);             // prefetch step 1
            FMAS(W0, W1, W2, W3, W4, dEa, dOa)     // step 0
            W0 = lds64(pX + 48);
            lds128(pD + 32, dEa, dOa);             // prefetch step 2
            FMAS(W1, W2, W3, W4, W5, dEb, dOb)     // step 1
            W1 = lds64(pX + 56);
            lds128(pD + 48, dEb, dOb);             // prefetch step 3
            FMAS(W2, W3, W4, W5, W0, dEa, dOa)     // step 2
            W2 = lds64(pX + 64);
            lds128(pD + 64, dEa, dOa);             // prefetch step 4
            FMAS(W3, W4, W5, W0, W1, dEb, dOb)     // step 3
            W3 = lds64(pX + 72);
            lds128(pD + 80, dEb, dOb);             // prefetch step 5
            FMAS(W4, W5, W0, W1, W2, dEa, dOa)     // step 4
            W4 = lds64(pX + 80);
            lds128(pD + 96, dEa, dOa);             // prefetch next group step 0
            FMAS(W5, W0, W1, W2, W3, dEb, dOb)     // step 5
            W5 = lds64(pX + 88);

            pX += 48;
            pD += 96;
        }

        // exact tail: first r steps of a group (rotation is 0 at entry;
        // uniform branches, taps beyond S are zero-padded so prefetch reads
        // past the end are harmless)
        if (r > 0) {
            lds128(pD + 16, dEb, dOb);
            FMAS(W0, W1, W2, W3, W4, dEa, dOa)
            if (r > 1) {
                W0 = lds64(pX + 48);
                lds128(pD + 32, dEa, dOa);
                FMAS(W1, W2, W3, W4, W5, dEb, dOb)
                if (r > 2) {
                    W1 = lds64(pX + 56);
                    lds128(pD + 48, dEb, dOb);
                    FMAS(W2, W3, W4, W5, W0, dEa, dOa)
                    if (r > 3) {
                        W2 = lds64(pX + 64);
                        lds128(pD + 64, dEa, dOa);
                        FMAS(W3, W4, W5, W0, W1, dEb, dOb)
                        if (r > 4) {
                            W3 = lds64(pX + 72);
                            FMAS(W4, W5, W0, W1, W2, dEa, dOa)
                        }
                    }
                }
            }
        }
#undef FMAS

        // exchange V0.lo with neighbor thread
        shV[tid] = ((float2*)&V0)->x;
        __syncthreads();

        if (tid < 120) {
            const float vlast = shV[tid + 1];   // V[10t+10]
            float2* __restrict__ o2 =
                (float2*)(outbase + (size_t)k * NOUT + 10 * tid);
            float2 e, va, vb, rr;
            e = *(float2*)&E0; va = *(float2*)&V0; vb = *(float2*)&V1;
            rr.x = sq * fabsf(e.x + va.y); rr.y = sq * fabsf(e.y + vb.x); o2[0] = rr;
            e = *(float2*)&E1; va = vb; vb = *(float2*)&V2;
            rr.x = sq * fabsf(e.x + va.y); rr.y = sq * fabsf(e.y + vb.x); o2[1] = rr;
            e = *(float2*)&E2; va = vb; vb = *(float2*)&V3;
            rr.x = sq * fabsf(e.x + va.y); rr.y = sq * fabsf(e.y + vb.x); o2[2] = rr;
            e = *(float2*)&E3; va = vb; vb = *(float2*)&V4;
            rr.x = sq * fabsf(e.x + va.y); rr.y = sq * fabsf(e.y + vb.x); o2[3] = rr;
            e = *(float2*)&E4; va = *(float2*)&V4;
            rr.x = sq * fabsf(e.x + va.y); rr.y = sq * fabsf(e.y + vlast); o2[4] = rr;
        }

        // stage next band's taps (static trip count; epilogue never reads shD4)
        if (k + 1 < NB) {
            const float2* __restrict__ dsrc = (const float2*)d_D[bk + 1];
            for (int idx = tid; idx < DH; idx += 128) {
                float2 p = dsrc[idx];
                shD4[idx] = make_float4(p.x, p.x, p.y, p.y);
            }
        }
        __syncthreads();
    }
}

// ---------------------------------------------------------------------------
extern "C" void kernel_launch(void* const* d_in, const int* in_sizes, int n_in,
                              void* d_out, int out_size) {
    (void)in_sizes; (void)n_in; (void)out_size;
    const float* ts  = (const float*)d_in[0];
    const float* tr  = (const float*)d_in[1];
    const float* lsp = (const float*)d_in[2];
    const float* bwp = (const float*)d_in[3];
    float* out = (float*)d_out;

    float* bands = out + (size_t)BATCH * REG * NB * NOUT;

    k_prep<<<BATCH * NB, DMAX>>>(tr, lsp, bwp, bands);
    k_cwt<<<BATCH * REG, 128>>>(ts, out);
}